// round 8
// baseline (speedup 1.0000x reference)
#include <cuda_runtime.h>
#include <cuda_bf16.h>
#include <cstdint>

// ---------------------------------------------------------------------------
// 4-layer GCN. GEMM: mma.sync.m16n8k16 bf16 split-precision (hi*hi + hi*lo +
// lo*hi, fp32 accum). CSR: fused convert+histogram (inline dtype probe),
// fused scan+norms, cursor fill. CSR structure build overlapped with GEMM0
// via capture-forked stream. Aggregation: CSR gather, float4, 2x unrolled.
// ---------------------------------------------------------------------------

#define NN 50000
#define NE 800000
#define SCAN_T 256
#define SCAN_G ((NN + SCAN_T - 1) / SCAN_T)   // 196

// scratch (device globals: no allocation allowed)
__device__ float g_bufA[NN * 128];
__device__ float g_bufB[NN * 128];
__device__ float g_out_norm[NN];
__device__ float g_in_norm[NN];
__device__ int   g_counts[3 * NN];            // [out_deg | in_deg | cursor]
__device__ int   g_row_ptr[NN + 1];
__device__ int   g_col_idx[NE];
__device__ int   g_src[NE];
__device__ int   g_dst[NE];
__device__ int   g_bsum[SCAN_G];

#define OUT_DEG(i) g_counts[(i)]
#define IN_DEG(i)  g_counts[NN + (i)]
#define CURSOR(i)  g_counts[2 * NN + (i)]

// ============================ PTX helpers ===================================

__device__ __forceinline__ uint32_t smem_u32(const void* p) {
    uint32_t a;
    asm("{ .reg .u64 t; cvta.to.shared.u64 t, %1; cvt.u32.u64 %0, t; }"
        : "=r"(a) : "l"(p));
    return a;
}

__device__ __forceinline__ void ldsm_x4(uint32_t* r, uint32_t addr) {
    asm volatile("ldmatrix.sync.aligned.m8n8.x4.shared.b16 {%0,%1,%2,%3}, [%4];"
                 : "=r"(r[0]), "=r"(r[1]), "=r"(r[2]), "=r"(r[3]) : "r"(addr));
}

__device__ __forceinline__ void ldsm_x4_t(uint32_t* r, uint32_t addr) {
    asm volatile("ldmatrix.sync.aligned.m8n8.x4.trans.shared.b16 {%0,%1,%2,%3}, [%4];"
                 : "=r"(r[0]), "=r"(r[1]), "=r"(r[2]), "=r"(r[3]) : "r"(addr));
}

__device__ __forceinline__ void mma_bf16(float* c, const uint32_t* a,
                                         uint32_t b0, uint32_t b1) {
    asm volatile(
        "mma.sync.aligned.m16n8k16.row.col.f32.bf16.bf16.f32 "
        "{%0,%1,%2,%3}, {%4,%5,%6,%7}, {%8,%9}, {%0,%1,%2,%3};"
        : "+f"(c[0]), "+f"(c[1]), "+f"(c[2]), "+f"(c[3])
        : "r"(a[0]), "r"(a[1]), "r"(a[2]), "r"(a[3]), "r"(b0), "r"(b1));
}

// =================== fused convert + histogram (probe inline) ===============
// JAX with x64 disabled silently emits int32 for edge_index despite jnp.int64.
// int64 node ids < 2^31 have zero high words at odd 32-bit positions; 64
// random int32 ids are ~never all zero there.

__global__ void conv_hist_kernel(const int* __restrict__ w, int e) {
    int flag = 0;
    if (threadIdx.x < 64) flag = (w[2 * threadIdx.x + 1] != 0);
    const int is64 = !__syncthreads_or(flag);

    const int i = blockIdx.x * blockDim.x + threadIdx.x;
    if (i >= e) return;
    int s, d;
    if (is64) {
        const long long* p = (const long long*)w;
        s = (int)p[i];
        d = (int)p[e + i];
    } else {
        s = w[i];
        d = w[e + i];
    }
    g_src[i] = s;
    g_dst[i] = d;
    atomicAdd(&OUT_DEG(s), 1);
    atomicAdd(&IN_DEG(d), 1);
}

// ---------------- fused block sums (for scan) + both norms ------------------

__global__ void scan_bsum_norms_kernel(int n) {
    __shared__ int sh[SCAN_T];
    const int tid = threadIdx.x;
    const int i = blockIdx.x * SCAN_T + tid;
    int din = 0;
    if (i < n) {
        din = IN_DEG(i);
        g_in_norm[i]  = rsqrtf((float)max(din, 1));
        g_out_norm[i] = rsqrtf((float)max(OUT_DEG(i), 1));
    }
    sh[tid] = din;
    __syncthreads();
    for (int off = 128; off > 0; off >>= 1) {
        if (tid < off) sh[tid] += sh[tid + off];
        __syncthreads();
    }
    if (tid == 0) g_bsum[blockIdx.x] = sh[0];
}

__global__ void scan_top_kernel() {
    __shared__ int sh[SCAN_G];
    const int tid = threadIdx.x;
    if (tid < SCAN_G) sh[tid] = g_bsum[tid];
    __syncthreads();
    if (tid == 0) {
        int run = 0;
        for (int b = 0; b < SCAN_G; b++) {
            int v = sh[b];
            g_bsum[b] = run;
            run += v;
        }
    }
}

__global__ void scan_fill_kernel(int n) {
    __shared__ int sh[SCAN_T];
    const int tid = threadIdx.x;
    const int i = blockIdx.x * SCAN_T + tid;
    const int d = (i < n) ? IN_DEG(i) : 0;
    sh[tid] = d;
    __syncthreads();
    for (int off = 1; off < SCAN_T; off <<= 1) {
        int v = (tid >= off) ? sh[tid - off] : 0;
        __syncthreads();
        sh[tid] += v;
        __syncthreads();
    }
    if (i < n) {
        const int incl = sh[tid];
        g_row_ptr[i] = g_bsum[blockIdx.x] + incl - d;
        if (i == n - 1) g_row_ptr[n] = g_bsum[blockIdx.x] + incl;
    }
}

__global__ void fill_csr_kernel(int e) {
    const int i = blockIdx.x * blockDim.x + threadIdx.x;
    if (i < e) {
        const int d = g_dst[i];
        const int pos = g_row_ptr[d] + atomicAdd(&CURSOR(d), 1);
        g_col_idx[pos] = g_src[i];
    }
}

// ================== bf16 split-precision mma.sync GEMM ======================
// C[n,FOUT] = (X[n,FIN] * out_norm[:,None]) @ W[FIN,FOUT], fp32 out.
// BM=128 rows/CTA, K chunked by 64. 8 warps: 4(m) x 2(n); warp = 32 x FOUT/2.
// smem rows padded +16B (odd multiples of 16B -> conflict-free ldmatrix).

union BF4 {
    unsigned long long u64;
    __nv_bfloat16 b[4];
};

template <int FIN, int FOUT>
__global__ __launch_bounds__(256, 1) void gemm_mma_kernel(
    const float* __restrict__ X, const float* __restrict__ W,
    float* __restrict__ C, int n)
{
    constexpr int BK = 64;
    constexpr int NCHUNK = FIN / BK;
    constexpr int RS_A = BK * 2 + 16;          // 144 B
    constexpr int RS_B = FOUT * 2 + 16;        // 272 or 144 B
    constexpr int A_SZ = 128 * RS_A;
    constexpr int B_SZ = BK * RS_B;
    constexpr int SM_A_HI = 0;
    constexpr int SM_A_LO = A_SZ;
    constexpr int SM_B_HI = 2 * A_SZ;
    constexpr int SM_B_LO = 2 * A_SZ + B_SZ;
    constexpr int WN = FOUT / 2;               // warp n-extent: 64 or 32
    constexpr int NT = WN / 16;                // x4.trans units: 4 or 2

    extern __shared__ char smem[];
    const uint32_t sb = smem_u32(smem);
    const int tid  = threadIdx.x;
    const int wid  = tid >> 5;
    const int lane = tid & 31;
    const int wm   = wid & 3;
    const int wn   = wid >> 2;
    const int row0 = blockIdx.x * 128;

    float acc[2][NT * 2][4];
#pragma unroll
    for (int mi = 0; mi < 2; mi++)
#pragma unroll
        for (int t = 0; t < NT * 2; t++)
#pragma unroll
            for (int j = 0; j < 4; j++) acc[mi][t][j] = 0.0f;

    for (int c = 0; c < NCHUNK; ++c) {
        const int k0 = c * BK;

        // ---- A chunk: 128 rows x 64 k, scale by out_norm, split hi/lo
        for (int idx = tid; idx < 128 * (BK / 4); idx += 256) {
            const int r  = idx >> 4;
            const int k  = (idx & 15) * 4;
            const int gr = row0 + r;
            float4 xv = make_float4(0.f, 0.f, 0.f, 0.f);
            float s = 0.f;
            if (gr < n) {
                xv = __ldg((const float4*)(X + (size_t)gr * FIN + k0 + k));
                s = g_out_norm[gr];
            }
            float v[4] = { xv.x * s, xv.y * s, xv.z * s, xv.w * s };
            BF4 hi, lo;
#pragma unroll
            for (int j = 0; j < 4; j++) {
                __nv_bfloat16 h = __float2bfloat16_rn(v[j]);
                hi.b[j] = h;
                lo.b[j] = __float2bfloat16_rn(v[j] - __bfloat162float(h));
            }
            const uint32_t off = (uint32_t)(r * RS_A + k * 2);
            *(unsigned long long*)(smem + SM_A_HI + off) = hi.u64;
            *(unsigned long long*)(smem + SM_A_LO + off) = lo.u64;
        }

        // ---- B chunk: 64 k-rows x FOUT, split hi/lo
        for (int idx = tid; idx < BK * (FOUT / 4); idx += 256) {
            const int k  = idx / (FOUT / 4);
            const int nn = (idx % (FOUT / 4)) * 4;
            float4 wv = __ldg((const float4*)(W + (size_t)(k0 + k) * FOUT + nn));
            float v[4] = { wv.x, wv.y, wv.z, wv.w };
            BF4 hi, lo;
#pragma unroll
            for (int j = 0; j < 4; j++) {
                __nv_bfloat16 h = __float2bfloat16_rn(v[j]);
                hi.b[j] = h;
                lo.b[j] = __float2bfloat16_rn(v[j] - __bfloat162float(h));
            }
            const uint32_t off = (uint32_t)(k * RS_B + nn * 2);
            *(unsigned long long*)(smem + SM_B_HI + off) = hi.u64;
            *(unsigned long long*)(smem + SM_B_LO + off) = lo.u64;
        }

        __syncthreads();

        // ---- MMA over 4 k-steps of 16
#pragma unroll
        for (int ks = 0; ks < 4; ks++) {
            const int kk = ks * 16;
            uint32_t a_hi[2][4], a_lo[2][4];
#pragma unroll
            for (int mi = 0; mi < 2; mi++) {
                const int r = wm * 32 + mi * 16 + (lane & 15);
                const int col = kk + ((lane >> 4) << 3);
                const uint32_t off = (uint32_t)(r * RS_A + col * 2);
                ldsm_x4(a_hi[mi], sb + SM_A_HI + off);
                ldsm_x4(a_lo[mi], sb + SM_A_LO + off);
            }
#pragma unroll
            for (int nt = 0; nt < NT; nt++) {
                const int k = kk + (lane & 15);
                const int nn = wn * WN + nt * 16 + ((lane >> 4) << 3);
                const uint32_t off = (uint32_t)(k * RS_B + nn * 2);
                uint32_t bh[4], bl[4];
                ldsm_x4_t(bh, sb + SM_B_HI + off);
                ldsm_x4_t(bl, sb + SM_B_LO + off);
#pragma unroll
                for (int mi = 0; mi < 2; mi++) {
                    mma_bf16(acc[mi][nt * 2 + 0], a_hi[mi], bh[0], bh[1]);
                    mma_bf16(acc[mi][nt * 2 + 1], a_hi[mi], bh[2], bh[3]);
                    mma_bf16(acc[mi][nt * 2 + 0], a_hi[mi], bl[0], bl[1]);
                    mma_bf16(acc[mi][nt * 2 + 1], a_hi[mi], bl[2], bl[3]);
                    mma_bf16(acc[mi][nt * 2 + 0], a_lo[mi], bh[0], bh[1]);
                    mma_bf16(acc[mi][nt * 2 + 1], a_lo[mi], bh[2], bh[3]);
                }
            }
        }
        __syncthreads();
    }

    // ---- epilogue: c0,c1 -> row g ; c2,c3 -> row g+8
    const int g = lane >> 2;
    const int q = lane & 3;
#pragma unroll
    for (int mi = 0; mi < 2; mi++) {
        const int rbase = row0 + wm * 32 + mi * 16;
#pragma unroll
        for (int t = 0; t < NT * 2; t++) {
            const int col = wn * WN + t * 8 + q * 2;
            const int r0 = rbase + g;
            const int r1 = rbase + g + 8;
            if (r0 < n)
                *(float2*)(C + (size_t)r0 * FOUT + col) =
                    make_float2(acc[mi][t][0], acc[mi][t][1]);
            if (r1 < n)
                *(float2*)(C + (size_t)r1 * FOUT + col) =
                    make_float2(acc[mi][t][2], acc[mi][t][3]);
        }
    }
}

// --------------------------- CSR aggregate ---------------------------------
// warp-per-node (F=128) or half-warp (F=64); float4 gathers; 2x unrolled.

template <int F, bool RELU>
__global__ void aggregate_kernel(const float4* __restrict__ H4,
                                 const float* __restrict__ bias,
                                 float4* __restrict__ out4, int n)
{
    constexpr int LPN = F / 4;
    constexpr int NPB = 128 / LPN;
    const int lane = threadIdx.x % LPN;
    const int slot = threadIdx.x / LPN;
    const int v = blockIdx.x * NPB + slot;
    if (v >= n) return;

    const int beg = g_row_ptr[v];
    const int end = g_row_ptr[v + 1];

    float4 acc0 = make_float4(0.f, 0.f, 0.f, 0.f);
    float4 acc1 = make_float4(0.f, 0.f, 0.f, 0.f);
    int e = beg;
    for (; e + 1 < end; e += 2) {
        const int s0 = g_col_idx[e];
        const int s1 = g_col_idx[e + 1];
        float4 h0 = __ldg(&H4[(size_t)s0 * LPN + lane]);
        float4 h1 = __ldg(&H4[(size_t)s1 * LPN + lane]);
        acc0.x += h0.x; acc0.y += h0.y; acc0.z += h0.z; acc0.w += h0.w;
        acc1.x += h1.x; acc1.y += h1.y; acc1.z += h1.z; acc1.w += h1.w;
    }
    if (e < end) {
        const int s = g_col_idx[e];
        float4 h = __ldg(&H4[(size_t)s * LPN + lane]);
        acc0.x += h.x; acc0.y += h.y; acc0.z += h.z; acc0.w += h.w;
    }
    acc0.x += acc1.x; acc0.y += acc1.y; acc0.z += acc1.z; acc0.w += acc1.w;

    const float nm = g_in_norm[v];
    const float4 b = __ldg(&((const float4*)bias)[lane]);
    float4 r = make_float4(acc0.x * nm + b.x, acc0.y * nm + b.y,
                           acc0.z * nm + b.z, acc0.w * nm + b.w);
    if (RELU) {
        r.x = fmaxf(r.x, 0.f); r.y = fmaxf(r.y, 0.f);
        r.z = fmaxf(r.z, 0.f); r.w = fmaxf(r.w, 0.f);
    }
    out4[(size_t)v * LPN + lane] = r;
}

// ------------------------------- launch ------------------------------------

extern "C" void kernel_launch(void* const* d_in, const int* in_sizes, int n_in,
                              void* d_out, int out_size)
{
    const float* x  = (const float*)d_in[0];
    const int*   ei = (const int*)d_in[1];
    const float* W0 = (const float*)d_in[2];
    const float* b0 = (const float*)d_in[3];
    const float* W1 = (const float*)d_in[4];
    const float* b1 = (const float*)d_in[5];
    const float* W2 = (const float*)d_in[6];
    const float* b2 = (const float*)d_in[7];
    const float* W3 = (const float*)d_in[8];
    const float* b3 = (const float*)d_in[9];
    float* out = (float*)d_out;

    const int e = in_sizes[1] / 2;        // 800000 edges
    const int n = in_sizes[0] / 256;      // 50000 nodes

    void* pA = nullptr;
    void* pB = nullptr;
    void* pC = nullptr;
    cudaGetSymbolAddress(&pA, g_bufA);
    cudaGetSymbolAddress(&pB, g_bufB);
    cudaGetSymbolAddress(&pC, g_counts);
    float* bufA = (float*)pA;
    float* bufB = (float*)pB;

    // one-time host-side setup (no device allocation)
    static bool inited = false;
    static cudaStream_t s2 = 0;
    static cudaEvent_t ev1 = 0, ev2 = 0;
    static bool have_fork = false;
    if (!inited) {
        inited = true;
        have_fork =
            (cudaStreamCreateWithFlags(&s2, cudaStreamNonBlocking) == cudaSuccess) &&
            (cudaEventCreateWithFlags(&ev1, cudaEventDisableTiming) == cudaSuccess) &&
            (cudaEventCreateWithFlags(&ev2, cudaEventDisableTiming) == cudaSuccess);

        const int smem_f128 = 2 * 128 * 144 + 2 * 64 * 272;  // 71680
        const int smem_f64  = 2 * 128 * 144 + 2 * 64 * 144;  // 55296
        cudaFuncSetAttribute(gemm_mma_kernel<256, 128>,
                             cudaFuncAttributeMaxDynamicSharedMemorySize, smem_f128);
        cudaFuncSetAttribute(gemm_mma_kernel<128, 128>,
                             cudaFuncAttributeMaxDynamicSharedMemorySize, smem_f128);
        cudaFuncSetAttribute(gemm_mma_kernel<128, 64>,
                             cudaFuncAttributeMaxDynamicSharedMemorySize, smem_f64);
    }
    const int smem_f128 = 2 * 128 * 144 + 2 * 64 * 272;
    const int smem_f64  = 2 * 128 * 144 + 2 * 64 * 144;

    const int TB = 256;
    const int eg = (e + TB - 1) / TB;
    const cudaStream_t sB = have_fork ? s2 : (cudaStream_t)0;

    // ---- setup: counts memset, fused convert+histogram, fused norms+bsum
    cudaMemsetAsync(pC, 0, sizeof(int) * 3 * NN, 0);
    conv_hist_kernel<<<eg, TB>>>(ei, e);
    scan_bsum_norms_kernel<<<SCAN_G, SCAN_T>>>(n);

    // ---- fork: CSR structure build (branch B) overlaps GEMM0 (branch A)
    if (have_fork) cudaEventRecord(ev1, 0);
    if (have_fork) cudaStreamWaitEvent(sB, ev1, 0);
    scan_top_kernel<<<1, SCAN_T, 0, sB>>>();
    scan_fill_kernel<<<SCAN_G, SCAN_T, 0, sB>>>(n);
    fill_csr_kernel<<<eg, TB, 0, sB>>>(e);
    if (have_fork) cudaEventRecord(ev2, sB);

    const int GB = (n + 127) / 128;   // 391

    // layer 0: 256 -> 128, relu (GEMM0 concurrent with CSR structure build)
    gemm_mma_kernel<256, 128><<<GB, 256, smem_f128>>>(x, W0, bufA, n);
    if (have_fork) cudaStreamWaitEvent(0, ev2, 0);
    aggregate_kernel<128, true><<<(n + 3) / 4, 128>>>((const float4*)bufA, b0, (float4*)bufB, n);

    // layer 1: 128 -> 128, relu
    gemm_mma_kernel<128, 128><<<GB, 256, smem_f128>>>(bufB, W1, bufA, n);
    aggregate_kernel<128, true><<<(n + 3) / 4, 128>>>((const float4*)bufA, b1, (float4*)bufB, n);

    // layer 2: 128 -> 128, relu
    gemm_mma_kernel<128, 128><<<GB, 256, smem_f128>>>(bufB, W2, bufA, n);
    aggregate_kernel<128, true><<<(n + 3) / 4, 128>>>((const float4*)bufA, b2, (float4*)bufB, n);

    // layer 3: 128 -> 64, no relu
    gemm_mma_kernel<128, 64><<<GB, 256, smem_f64>>>(bufB, W3, bufA, n);
    aggregate_kernel<64, false><<<(n + 7) / 8, 128>>>((const float4*)bufA, b3, (float4*)out, n);
}

// round 10
// speedup vs baseline: 1.0277x; 1.0277x over previous
#include <cuda_runtime.h>
#include <cuda_bf16.h>
#include <cuda_fp16.h>
#include <cstdint>

// ---------------------------------------------------------------------------
// 4-layer GCN. GEMM: mma.sync.m16n8k16 bf16 split-precision (hi*hi + hi*lo +
// lo*hi, fp32 accum), output h stored fp16 (halves gather traffic; all sums
// stay fp32). CSR: fused convert+histogram (inline dtype probe), fused
// scan+norms, scan_fill with inline top-level prefix, cursor fill.
// Aggregation: CSR gather of fp16 h, fp32 accumulate, fp32 output.
// ---------------------------------------------------------------------------

#define NN 50000
#define NE 800000
#define SCAN_T 256
#define SCAN_G ((NN + SCAN_T - 1) / SCAN_T)   // 196

// scratch (device globals: no allocation allowed)
__device__ __half g_h16[NN * 128];            // GEMM output, pre-aggregation
__device__ float  g_bufA[NN * 128];           // aggregate output / GEMM input
__device__ float  g_out_norm[NN];
__device__ float  g_in_norm[NN];
__device__ int    g_counts[3 * NN];           // [out_deg | in_deg | cursor]
__device__ int    g_row_ptr[NN + 1];
__device__ int    g_col_idx[NE];
__device__ int    g_src[NE];
__device__ int    g_dst[NE];
__device__ int    g_bsum[SCAN_G];

#define OUT_DEG(i) g_counts[(i)]
#define IN_DEG(i)  g_counts[NN + (i)]
#define CURSOR(i)  g_counts[2 * NN + (i)]

// ============================ PTX helpers ===================================

__device__ __forceinline__ uint32_t smem_u32(const void* p) {
    uint32_t a;
    asm("{ .reg .u64 t; cvta.to.shared.u64 t, %1; cvt.u32.u64 %0, t; }"
        : "=r"(a) : "l"(p));
    return a;
}

__device__ __forceinline__ void ldsm_x4(uint32_t* r, uint32_t addr) {
    asm volatile("ldmatrix.sync.aligned.m8n8.x4.shared.b16 {%0,%1,%2,%3}, [%4];"
                 : "=r"(r[0]), "=r"(r[1]), "=r"(r[2]), "=r"(r[3]) : "r"(addr));
}

__device__ __forceinline__ void ldsm_x4_t(uint32_t* r, uint32_t addr) {
    asm volatile("ldmatrix.sync.aligned.m8n8.x4.trans.shared.b16 {%0,%1,%2,%3}, [%4];"
                 : "=r"(r[0]), "=r"(r[1]), "=r"(r[2]), "=r"(r[3]) : "r"(addr));
}

__device__ __forceinline__ void mma_bf16(float* c, const uint32_t* a,
                                         uint32_t b0, uint32_t b1) {
    asm volatile(
        "mma.sync.aligned.m16n8k16.row.col.f32.bf16.bf16.f32 "
        "{%0,%1,%2,%3}, {%4,%5,%6,%7}, {%8,%9}, {%0,%1,%2,%3};"
        : "+f"(c[0]), "+f"(c[1]), "+f"(c[2]), "+f"(c[3])
        : "r"(a[0]), "r"(a[1]), "r"(a[2]), "r"(a[3]), "r"(b0), "r"(b1));
}

// =================== fused convert + histogram (probe inline) ===============
// JAX with x64 disabled silently emits int32 for edge_index despite jnp.int64.
// int64 node ids < 2^31 have zero high words at odd 32-bit positions; 64
// random int32 ids are ~never all zero there.

__global__ void conv_hist_kernel(const int* __restrict__ w, int e) {
    int flag = 0;
    if (threadIdx.x < 64) flag = (w[2 * threadIdx.x + 1] != 0);
    const int is64 = !__syncthreads_or(flag);

    const int i = blockIdx.x * blockDim.x + threadIdx.x;
    if (i >= e) return;
    int s, d;
    if (is64) {
        const long long* p = (const long long*)w;
        s = (int)p[i];
        d = (int)p[e + i];
    } else {
        s = w[i];
        d = w[e + i];
    }
    g_src[i] = s;
    g_dst[i] = d;
    atomicAdd(&OUT_DEG(s), 1);
    atomicAdd(&IN_DEG(d), 1);
}

// ---------------- fused block sums (for scan) + both norms ------------------

__global__ void scan_bsum_norms_kernel(int n) {
    __shared__ int sh[SCAN_T];
    const int tid = threadIdx.x;
    const int i = blockIdx.x * SCAN_T + tid;
    int din = 0;
    if (i < n) {
        din = IN_DEG(i);
        g_in_norm[i]  = rsqrtf((float)max(din, 1));
        g_out_norm[i] = rsqrtf((float)max(OUT_DEG(i), 1));
    }
    sh[tid] = din;
    __syncthreads();
    for (int off = 128; off > 0; off >>= 1) {
        if (tid < off) sh[tid] += sh[tid + off];
        __syncthreads();
    }
    if (tid == 0) g_bsum[blockIdx.x] = sh[0];
}

// scan_fill with inline top-level prefix (sums g_bsum[0..blockIdx) per block)

__global__ void scan_fill_kernel(int n) {
    __shared__ int sh[SCAN_T];
    __shared__ int base_sh;
    const int tid = threadIdx.x;

    // block-level exclusive base: reduce g_bsum[0..blockIdx.x)
    int partial = 0;
    for (int b = tid; b < blockIdx.x; b += SCAN_T) partial += g_bsum[b];
    sh[tid] = partial;
    __syncthreads();
    for (int off = 128; off > 0; off >>= 1) {
        if (tid < off) sh[tid] += sh[tid + off];
        __syncthreads();
    }
    if (tid == 0) base_sh = sh[0];
    __syncthreads();
    const int base = base_sh;
    __syncthreads();

    // intra-block scan of in_deg
    const int i = blockIdx.x * SCAN_T + tid;
    const int d = (i < n) ? IN_DEG(i) : 0;
    sh[tid] = d;
    __syncthreads();
    for (int off = 1; off < SCAN_T; off <<= 1) {
        int v = (tid >= off) ? sh[tid - off] : 0;
        __syncthreads();
        sh[tid] += v;
        __syncthreads();
    }
    if (i < n) {
        const int incl = sh[tid];
        g_row_ptr[i] = base + incl - d;
        if (i == n - 1) g_row_ptr[n] = base + incl;
    }
}

__global__ void fill_csr_kernel(int e) {
    const int i = blockIdx.x * blockDim.x + threadIdx.x;
    if (i < e) {
        const int d = g_dst[i];
        const int pos = g_row_ptr[d] + atomicAdd(&CURSOR(d), 1);
        g_col_idx[pos] = g_src[i];
    }
}

// ================== bf16 split-precision mma.sync GEMM ======================
// C16[n,FOUT] = fp16( (X[n,FIN] * out_norm[:,None]) @ W[FIN,FOUT] )
// BM=128 rows/CTA, K chunked by 64. 8 warps: 4(m) x 2(n); warp = 32 x FOUT/2.
// smem rows padded +16B (odd multiples of 16B -> conflict-free ldmatrix).

union BF4 {
    unsigned long long u64;
    __nv_bfloat16 b[4];
};

template <int FIN, int FOUT>
__global__ __launch_bounds__(256, 1) void gemm_mma_kernel(
    const float* __restrict__ X, const float* __restrict__ W,
    __half* __restrict__ C16, int n)
{
    constexpr int BK = 64;
    constexpr int NCHUNK = FIN / BK;
    constexpr int RS_A = BK * 2 + 16;          // 144 B
    constexpr int RS_B = FOUT * 2 + 16;        // 272 or 144 B
    constexpr int A_SZ = 128 * RS_A;
    constexpr int B_SZ = BK * RS_B;
    constexpr int SM_A_HI = 0;
    constexpr int SM_A_LO = A_SZ;
    constexpr int SM_B_HI = 2 * A_SZ;
    constexpr int SM_B_LO = 2 * A_SZ + B_SZ;
    constexpr int WN = FOUT / 2;               // warp n-extent: 64 or 32
    constexpr int NT = WN / 16;                // x4.trans units: 4 or 2

    extern __shared__ char smem[];
    const uint32_t sb = smem_u32(smem);
    const int tid  = threadIdx.x;
    const int wid  = tid >> 5;
    const int lane = tid & 31;
    const int wm   = wid & 3;
    const int wn   = wid >> 2;
    const int row0 = blockIdx.x * 128;

    float acc[2][NT * 2][4];
#pragma unroll
    for (int mi = 0; mi < 2; mi++)
#pragma unroll
        for (int t = 0; t < NT * 2; t++)
#pragma unroll
            for (int j = 0; j < 4; j++) acc[mi][t][j] = 0.0f;

    for (int c = 0; c < NCHUNK; ++c) {
        const int k0 = c * BK;

        // ---- A chunk: 128 rows x 64 k, scale by out_norm, split hi/lo
        for (int idx = tid; idx < 128 * (BK / 4); idx += 256) {
            const int r  = idx >> 4;
            const int k  = (idx & 15) * 4;
            const int gr = row0 + r;
            float4 xv = make_float4(0.f, 0.f, 0.f, 0.f);
            float s = 0.f;
            if (gr < n) {
                xv = __ldg((const float4*)(X + (size_t)gr * FIN + k0 + k));
                s = g_out_norm[gr];
            }
            float v[4] = { xv.x * s, xv.y * s, xv.z * s, xv.w * s };
            BF4 hi, lo;
#pragma unroll
            for (int j = 0; j < 4; j++) {
                __nv_bfloat16 h = __float2bfloat16_rn(v[j]);
                hi.b[j] = h;
                lo.b[j] = __float2bfloat16_rn(v[j] - __bfloat162float(h));
            }
            const uint32_t off = (uint32_t)(r * RS_A + k * 2);
            *(unsigned long long*)(smem + SM_A_HI + off) = hi.u64;
            *(unsigned long long*)(smem + SM_A_LO + off) = lo.u64;
        }

        // ---- B chunk: 64 k-rows x FOUT, split hi/lo
        for (int idx = tid; idx < BK * (FOUT / 4); idx += 256) {
            const int k  = idx / (FOUT / 4);
            const int nn = (idx % (FOUT / 4)) * 4;
            float4 wv = __ldg((const float4*)(W + (size_t)(k0 + k) * FOUT + nn));
            float v[4] = { wv.x, wv.y, wv.z, wv.w };
            BF4 hi, lo;
#pragma unroll
            for (int j = 0; j < 4; j++) {
                __nv_bfloat16 h = __float2bfloat16_rn(v[j]);
                hi.b[j] = h;
                lo.b[j] = __float2bfloat16_rn(v[j] - __bfloat162float(h));
            }
            const uint32_t off = (uint32_t)(k * RS_B + nn * 2);
            *(unsigned long long*)(smem + SM_B_HI + off) = hi.u64;
            *(unsigned long long*)(smem + SM_B_LO + off) = lo.u64;
        }

        __syncthreads();

        // ---- MMA over 4 k-steps of 16
#pragma unroll
        for (int ks = 0; ks < 4; ks++) {
            const int kk = ks * 16;
            uint32_t a_hi[2][4], a_lo[2][4];
#pragma unroll
            for (int mi = 0; mi < 2; mi++) {
                const int r = wm * 32 + mi * 16 + (lane & 15);
                const int col = kk + ((lane >> 4) << 3);
                const uint32_t off = (uint32_t)(r * RS_A + col * 2);
                ldsm_x4(a_hi[mi], sb + SM_A_HI + off);
                ldsm_x4(a_lo[mi], sb + SM_A_LO + off);
            }
#pragma unroll
            for (int nt = 0; nt < NT; nt++) {
                const int k = kk + (lane & 15);
                const int nn = wn * WN + nt * 16 + ((lane >> 4) << 3);
                const uint32_t off = (uint32_t)(k * RS_B + nn * 2);
                uint32_t bh[4], bl[4];
                ldsm_x4_t(bh, sb + SM_B_HI + off);
                ldsm_x4_t(bl, sb + SM_B_LO + off);
#pragma unroll
                for (int mi = 0; mi < 2; mi++) {
                    mma_bf16(acc[mi][nt * 2 + 0], a_hi[mi], bh[0], bh[1]);
                    mma_bf16(acc[mi][nt * 2 + 1], a_hi[mi], bh[2], bh[3]);
                    mma_bf16(acc[mi][nt * 2 + 0], a_hi[mi], bl[0], bl[1]);
                    mma_bf16(acc[mi][nt * 2 + 1], a_hi[mi], bl[2], bl[3]);
                    mma_bf16(acc[mi][nt * 2 + 0], a_lo[mi], bh[0], bh[1]);
                    mma_bf16(acc[mi][nt * 2 + 1], a_lo[mi], bh[2], bh[3]);
                }
            }
        }
        __syncthreads();
    }

    // ---- epilogue: c0,c1 -> (row g, col..col+1) ; c2,c3 -> row g+8; fp16 out
    const int g = lane >> 2;
    const int q = lane & 3;
#pragma unroll
    for (int mi = 0; mi < 2; mi++) {
        const int rbase = row0 + wm * 32 + mi * 16;
#pragma unroll
        for (int t = 0; t < NT * 2; t++) {
            const int col = wn * WN + t * 8 + q * 2;
            const int r0 = rbase + g;
            const int r1 = rbase + g + 8;
            if (r0 < n)
                *(__half2*)(C16 + (size_t)r0 * FOUT + col) =
                    __floats2half2_rn(acc[mi][t][0], acc[mi][t][1]);
            if (r1 < n)
                *(__half2*)(C16 + (size_t)r1 * FOUT + col) =
                    __floats2half2_rn(acc[mi][t][2], acc[mi][t][3]);
        }
    }
}

// --------------------------- CSR aggregate (fp16 h) -------------------------
// out[v,f] = maybe_relu( in_norm[v] * sum_{e in row v} h16[col_idx[e], f] + b[f] )
// LPN lanes per node, each lane owns 4 features (uint2 = 4 halves per edge).
// fp32 accumulation; fp32 output.

template <int F, bool RELU>
__global__ void aggregate_kernel(const __half* __restrict__ H,
                                 const float* __restrict__ bias,
                                 float4* __restrict__ out4, int n)
{
    constexpr int LPN = F / 4;         // 32 or 16
    constexpr int NPB = 128 / LPN;     // 4 or 8
    const int lane = threadIdx.x % LPN;
    const int slot = threadIdx.x / LPN;
    const int v = blockIdx.x * NPB + slot;
    if (v >= n) return;

    const int beg = g_row_ptr[v];
    const int end = g_row_ptr[v + 1];

    float4 acc0 = make_float4(0.f, 0.f, 0.f, 0.f);
    float4 acc1 = make_float4(0.f, 0.f, 0.f, 0.f);
    int e = beg;
    for (; e + 1 < end; e += 2) {
        const int s0 = g_col_idx[e];
        const int s1 = g_col_idx[e + 1];
        const uint2 u0 = __ldg((const uint2*)(H + (size_t)s0 * F) + lane);
        const uint2 u1 = __ldg((const uint2*)(H + (size_t)s1 * F) + lane);
        const float2 a = __half22float2(*(const __half2*)&u0.x);
        const float2 b = __half22float2(*(const __half2*)&u0.y);
        const float2 c = __half22float2(*(const __half2*)&u1.x);
        const float2 d = __half22float2(*(const __half2*)&u1.y);
        acc0.x += a.x; acc0.y += a.y; acc0.z += b.x; acc0.w += b.y;
        acc1.x += c.x; acc1.y += c.y; acc1.z += d.x; acc1.w += d.y;
    }
    if (e < end) {
        const int s = g_col_idx[e];
        const uint2 u = __ldg((const uint2*)(H + (size_t)s * F) + lane);
        const float2 a = __half22float2(*(const __half2*)&u.x);
        const float2 b = __half22float2(*(const __half2*)&u.y);
        acc0.x += a.x; acc0.y += a.y; acc0.z += b.x; acc0.w += b.y;
    }
    acc0.x += acc1.x; acc0.y += acc1.y; acc0.z += acc1.z; acc0.w += acc1.w;

    const float nm = g_in_norm[v];
    const float4 b4 = __ldg(&((const float4*)bias)[lane]);
    float4 r = make_float4(acc0.x * nm + b4.x, acc0.y * nm + b4.y,
                           acc0.z * nm + b4.z, acc0.w * nm + b4.w);
    if (RELU) {
        r.x = fmaxf(r.x, 0.f); r.y = fmaxf(r.y, 0.f);
        r.z = fmaxf(r.z, 0.f); r.w = fmaxf(r.w, 0.f);
    }
    out4[(size_t)v * LPN + lane] = r;
}

// ------------------------------- launch ------------------------------------

extern "C" void kernel_launch(void* const* d_in, const int* in_sizes, int n_in,
                              void* d_out, int out_size)
{
    const float* x  = (const float*)d_in[0];
    const int*   ei = (const int*)d_in[1];
    const float* W0 = (const float*)d_in[2];
    const float* b0 = (const float*)d_in[3];
    const float* W1 = (const float*)d_in[4];
    const float* b1 = (const float*)d_in[5];
    const float* W2 = (const float*)d_in[6];
    const float* b2 = (const float*)d_in[7];
    const float* W3 = (const float*)d_in[8];
    const float* b3 = (const float*)d_in[9];
    float* out = (float*)d_out;

    const int e = in_sizes[1] / 2;        // 800000 edges
    const int n = in_sizes[0] / 256;      // 50000 nodes

    void* pH = nullptr;
    void* pA = nullptr;
    void* pC = nullptr;
    cudaGetSymbolAddress(&pH, g_h16);
    cudaGetSymbolAddress(&pA, g_bufA);
    cudaGetSymbolAddress(&pC, g_counts);
    __half* h16 = (__half*)pH;
    float* bufA = (float*)pA;

    const int smem_f128 = 2 * 128 * 144 + 2 * 64 * 272;  // 71680
    const int smem_f64  = 2 * 128 * 144 + 2 * 64 * 144;  // 55296

    static bool inited = false;
    if (!inited) {
        inited = true;
        cudaFuncSetAttribute(gemm_mma_kernel<256, 128>,
                             cudaFuncAttributeMaxDynamicSharedMemorySize, smem_f128);
        cudaFuncSetAttribute(gemm_mma_kernel<128, 128>,
                             cudaFuncAttributeMaxDynamicSharedMemorySize, smem_f128);
        cudaFuncSetAttribute(gemm_mma_kernel<128, 64>,
                             cudaFuncAttributeMaxDynamicSharedMemorySize, smem_f64);
    }

    const int TB = 256;
    const int eg = (e + TB - 1) / TB;

    // ---- setup: counts memset, convert+histogram, norms+bsum, scan, fill
    cudaMemsetAsync(pC, 0, sizeof(int) * 3 * NN, 0);
    conv_hist_kernel<<<eg, TB>>>(ei, e);
    scan_bsum_norms_kernel<<<SCAN_G, SCAN_T>>>(n);
    scan_fill_kernel<<<SCAN_G, SCAN_T>>>(n);
    fill_csr_kernel<<<eg, TB>>>(e);

    const int GB = (n + 127) / 128;   // 391

    // layer 0: 256 -> 128, relu
    gemm_mma_kernel<256, 128><<<GB, 256, smem_f128>>>(x, W0, h16, n);
    aggregate_kernel<128, true><<<(n + 3) / 4, 128>>>(h16, b0, (float4*)bufA, n);

    // layer 1: 128 -> 128, relu
    gemm_mma_kernel<128, 128><<<GB, 256, smem_f128>>>(bufA, W1, h16, n);
    aggregate_kernel<128, true><<<(n + 3) / 4, 128>>>(h16, b1, (float4*)bufA, n);

    // layer 2: 128 -> 128, relu
    gemm_mma_kernel<128, 128><<<GB, 256, smem_f128>>>(bufA, W2, h16, n);
    aggregate_kernel<128, true><<<(n + 3) / 4, 128>>>(h16, b2, (float4*)bufA, n);

    // layer 3: 128 -> 64, no relu, fp32 out
    gemm_mma_kernel<128, 64><<<GB, 256, smem_f64>>>(bufA, W3, h16, n);
    aggregate_kernel<64, false><<<(n + 7) / 8, 128>>>(h16, b3, (float4*)out, n);
}

// round 11
// speedup vs baseline: 1.0357x; 1.0078x over previous
#include <cuda_runtime.h>
#include <cuda_bf16.h>
#include <cuda_fp16.h>
#include <cstdint>

// ---------------------------------------------------------------------------
// 4-layer GCN. GEMM: mma.sync.m16n8k16 bf16 split-precision (hi*hi + hi*lo +
// lo*hi, fp32 accum), h stored fp16. Aggregates emit next layer's A operand
// directly as pre-scaled bf16 hi/lo (relu -> *out_norm -> split), so GEMMs
// 1-3 skip fp32 A conversion. Setup slimmed to 4 launches: memset, hist
// (inline dtype probe), scan_fill (norms + base + scan fused), fill_csr
// (re-reads raw edges with inline probe).
// ---------------------------------------------------------------------------

#define NN 50000
#define NE 800000
#define SCAN_T 256
#define SCAN_G ((NN + SCAN_T - 1) / SCAN_T)   // 196

// scratch (device globals: no allocation allowed)
__device__ __half         g_h16[NN * 128];    // GEMM output, pre-aggregation
__device__ __nv_bfloat16  g_ahi[NN * 128];    // aggregate out: bf16 hi
__device__ __nv_bfloat16  g_alo[NN * 128];    // aggregate out: bf16 lo
__device__ float  g_out_norm[NN];
__device__ float  g_in_norm[NN];
__device__ int    g_counts[3 * NN];           // [out_deg | in_deg | cursor]
__device__ int    g_row_ptr[NN + 1];
__device__ int    g_col_idx[NE];

#define OUT_DEG(i) g_counts[(i)]
#define IN_DEG(i)  g_counts[NN + (i)]
#define CURSOR(i)  g_counts[2 * NN + (i)]

// ============================ PTX helpers ===================================

__device__ __forceinline__ uint32_t smem_u32(const void* p) {
    uint32_t a;
    asm("{ .reg .u64 t; cvta.to.shared.u64 t, %1; cvt.u32.u64 %0, t; }"
        : "=r"(a) : "l"(p));
    return a;
}

__device__ __forceinline__ void ldsm_x4(uint32_t* r, uint32_t addr) {
    asm volatile("ldmatrix.sync.aligned.m8n8.x4.shared.b16 {%0,%1,%2,%3}, [%4];"
                 : "=r"(r[0]), "=r"(r[1]), "=r"(r[2]), "=r"(r[3]) : "r"(addr));
}

__device__ __forceinline__ void ldsm_x4_t(uint32_t* r, uint32_t addr) {
    asm volatile("ldmatrix.sync.aligned.m8n8.x4.trans.shared.b16 {%0,%1,%2,%3}, [%4];"
                 : "=r"(r[0]), "=r"(r[1]), "=r"(r[2]), "=r"(r[3]) : "r"(addr));
}

__device__ __forceinline__ void mma_bf16(float* c, const uint32_t* a,
                                         uint32_t b0, uint32_t b1) {
    asm volatile(
        "mma.sync.aligned.m16n8k16.row.col.f32.bf16.bf16.f32 "
        "{%0,%1,%2,%3}, {%4,%5,%6,%7}, {%8,%9}, {%0,%1,%2,%3};"
        : "+f"(c[0]), "+f"(c[1]), "+f"(c[2]), "+f"(c[3])
        : "r"(a[0]), "r"(a[1]), "r"(a[2]), "r"(a[3]), "r"(b0), "r"(b1));
}

// =================== histogram with inline dtype probe ======================
// JAX with x64 disabled silently emits int32 for edge_index despite jnp.int64.
// int64 node ids < 2^31 have zero high words at odd 32-bit positions; 64
// random int32 ids are ~never all zero there.

__device__ __forceinline__ int probe_is64(const int* __restrict__ w) {
    int flag = 0;
    if (threadIdx.x < 64) flag = (w[2 * threadIdx.x + 1] != 0);
    return !__syncthreads_or(flag);
}

__device__ __forceinline__ void load_edge(const int* __restrict__ w, int e,
                                          int is64, int i, int& s, int& d) {
    if (is64) {
        const long long* p = (const long long*)w;
        s = (int)p[i];
        d = (int)p[e + i];
    } else {
        s = w[i];
        d = w[e + i];
    }
}

__global__ void hist_kernel(const int* __restrict__ w, int e) {
    const int is64 = probe_is64(w);
    const int i = blockIdx.x * blockDim.x + threadIdx.x;
    if (i >= e) return;
    int s, d;
    load_edge(w, e, is64, i, s, d);
    atomicAdd(&OUT_DEG(s), 1);
    atomicAdd(&IN_DEG(d), 1);
}

// ---- fused: norms + per-block exclusive base (direct IN_DEG sum) + scan ----

__global__ void scan_fill_kernel(int n) {
    __shared__ int sh[SCAN_T];
    __shared__ int base_sh;
    const int tid = threadIdx.x;

    // block base: sum IN_DEG[0 .. blockStart)
    const int blk_start = blockIdx.x * SCAN_T;
    int partial = 0;
    for (int i = tid; i < blk_start; i += SCAN_T) partial += IN_DEG(i);
    sh[tid] = partial;
    __syncthreads();
    for (int off = 128; off > 0; off >>= 1) {
        if (tid < off) sh[tid] += sh[tid + off];
        __syncthreads();
    }
    if (tid == 0) base_sh = sh[0];
    __syncthreads();
    const int base = base_sh;
    __syncthreads();

    // norms + intra-block scan of in_deg
    const int i = blk_start + tid;
    int d = 0;
    if (i < n) {
        d = IN_DEG(i);
        g_in_norm[i]  = rsqrtf((float)max(d, 1));
        g_out_norm[i] = rsqrtf((float)max(OUT_DEG(i), 1));
    }
    sh[tid] = d;
    __syncthreads();
    for (int off = 1; off < SCAN_T; off <<= 1) {
        int v = (tid >= off) ? sh[tid - off] : 0;
        __syncthreads();
        sh[tid] += v;
        __syncthreads();
    }
    if (i < n) {
        const int incl = sh[tid];
        g_row_ptr[i] = base + incl - d;
        if (i == n - 1) g_row_ptr[n] = base + incl;
    }
}

__global__ void fill_csr_kernel(const int* __restrict__ w, int e) {
    const int is64 = probe_is64(w);
    const int i = blockIdx.x * blockDim.x + threadIdx.x;
    if (i >= e) return;
    int s, d;
    load_edge(w, e, is64, i, s, d);
    const int pos = g_row_ptr[d] + atomicAdd(&CURSOR(d), 1);
    g_col_idx[pos] = s;
}

// ================== bf16 split-precision mma.sync GEMM ======================
// C16[n,FOUT] = fp16( A @ W[FIN,FOUT] ), A = X*out_norm (fp32 path, A16=false)
// or pre-split bf16 hi/lo (A16=true, produced by aggregate).
// BM=128 rows/CTA, K chunked by 64. 8 warps: 4(m) x 2(n); warp = 32 x FOUT/2.
// smem rows padded +16B (odd multiples of 16B -> conflict-free ldmatrix).

union BF4 {
    unsigned long long u64;
    __nv_bfloat16 b[4];
};

template <int FIN, int FOUT, bool A16>
__global__ __launch_bounds__(256, 1) void gemm_mma_kernel(
    const float* __restrict__ X,
    const __nv_bfloat16* __restrict__ Ahi,
    const __nv_bfloat16* __restrict__ Alo,
    const float* __restrict__ W,
    __half* __restrict__ C16, int n)
{
    constexpr int BK = 64;
    constexpr int NCHUNK = FIN / BK;
    constexpr int RS_A = BK * 2 + 16;          // 144 B
    constexpr int RS_B = FOUT * 2 + 16;        // 272 or 144 B
    constexpr int A_SZ = 128 * RS_A;
    constexpr int B_SZ = BK * RS_B;
    constexpr int SM_A_HI = 0;
    constexpr int SM_A_LO = A_SZ;
    constexpr int SM_B_HI = 2 * A_SZ;
    constexpr int SM_B_LO = 2 * A_SZ + B_SZ;
    constexpr int WN = FOUT / 2;               // warp n-extent: 64 or 32
    constexpr int NT = WN / 16;                // x4.trans units: 4 or 2

    extern __shared__ char smem[];
    const uint32_t sb = smem_u32(smem);
    const int tid  = threadIdx.x;
    const int wid  = tid >> 5;
    const int lane = tid & 31;
    const int wm   = wid & 3;
    const int wn   = wid >> 2;
    const int row0 = blockIdx.x * 128;

    float acc[2][NT * 2][4];
#pragma unroll
    for (int mi = 0; mi < 2; mi++)
#pragma unroll
        for (int t = 0; t < NT * 2; t++)
#pragma unroll
            for (int j = 0; j < 4; j++) acc[mi][t][j] = 0.0f;

    for (int c = 0; c < NCHUNK; ++c) {
        const int k0 = c * BK;

        // ---- A chunk: 128 rows x 64 k -> smem hi/lo
        for (int idx = tid; idx < 128 * (BK / 4); idx += 256) {
            const int r  = idx >> 4;
            const int k  = (idx & 15) * 4;
            const int gr = row0 + r;
            const uint32_t off = (uint32_t)(r * RS_A + k * 2);
            if (A16) {
                unsigned long long hi = 0ull, lo = 0ull;
                if (gr < n) {
                    hi = *(const unsigned long long*)(Ahi + (size_t)gr * FIN + k0 + k);
                    lo = *(const unsigned long long*)(Alo + (size_t)gr * FIN + k0 + k);
                }
                *(unsigned long long*)(smem + SM_A_HI + off) = hi;
                *(unsigned long long*)(smem + SM_A_LO + off) = lo;
            } else {
                float4 xv = make_float4(0.f, 0.f, 0.f, 0.f);
                float s = 0.f;
                if (gr < n) {
                    xv = __ldg((const float4*)(X + (size_t)gr * FIN + k0 + k));
                    s = g_out_norm[gr];
                }
                float v[4] = { xv.x * s, xv.y * s, xv.z * s, xv.w * s };
                BF4 hi, lo;
#pragma unroll
                for (int j = 0; j < 4; j++) {
                    __nv_bfloat16 h = __float2bfloat16_rn(v[j]);
                    hi.b[j] = h;
                    lo.b[j] = __float2bfloat16_rn(v[j] - __bfloat162float(h));
                }
                *(unsigned long long*)(smem + SM_A_HI + off) = hi.u64;
                *(unsigned long long*)(smem + SM_A_LO + off) = lo.u64;
            }
        }

        // ---- B chunk: 64 k-rows x FOUT, split hi/lo
        for (int idx = tid; idx < BK * (FOUT / 4); idx += 256) {
            const int k  = idx / (FOUT / 4);
            const int nn = (idx % (FOUT / 4)) * 4;
            float4 wv = __ldg((const float4*)(W + (size_t)(k0 + k) * FOUT + nn));
            float v[4] = { wv.x, wv.y, wv.z, wv.w };
            BF4 hi, lo;
#pragma unroll
            for (int j = 0; j < 4; j++) {
                __nv_bfloat16 h = __float2bfloat16_rn(v[j]);
                hi.b[j] = h;
                lo.b[j] = __float2bfloat16_rn(v[j] - __bfloat162float(h));
            }
            const uint32_t off = (uint32_t)(k * RS_B + nn * 2);
            *(unsigned long long*)(smem + SM_B_HI + off) = hi.u64;
            *(unsigned long long*)(smem + SM_B_LO + off) = lo.u64;
        }

        __syncthreads();

        // ---- MMA over 4 k-steps of 16
#pragma unroll
        for (int ks = 0; ks < 4; ks++) {
            const int kk = ks * 16;
            uint32_t a_hi[2][4], a_lo[2][4];
#pragma unroll
            for (int mi = 0; mi < 2; mi++) {
                const int r = wm * 32 + mi * 16 + (lane & 15);
                const int col = kk + ((lane >> 4) << 3);
                const uint32_t off = (uint32_t)(r * RS_A + col * 2);
                ldsm_x4(a_hi[mi], sb + SM_A_HI + off);
                ldsm_x4(a_lo[mi], sb + SM_A_LO + off);
            }
#pragma unroll
            for (int nt = 0; nt < NT; nt++) {
                const int k = kk + (lane & 15);
                const int nn = wn * WN + nt * 16 + ((lane >> 4) << 3);
                const uint32_t off = (uint32_t)(k * RS_B + nn * 2);
                uint32_t bh[4], bl[4];
                ldsm_x4_t(bh, sb + SM_B_HI + off);
                ldsm_x4_t(bl, sb + SM_B_LO + off);
#pragma unroll
                for (int mi = 0; mi < 2; mi++) {
                    mma_bf16(acc[mi][nt * 2 + 0], a_hi[mi], bh[0], bh[1]);
                    mma_bf16(acc[mi][nt * 2 + 1], a_hi[mi], bh[2], bh[3]);
                    mma_bf16(acc[mi][nt * 2 + 0], a_hi[mi], bl[0], bl[1]);
                    mma_bf16(acc[mi][nt * 2 + 1], a_hi[mi], bl[2], bl[3]);
                    mma_bf16(acc[mi][nt * 2 + 0], a_lo[mi], bh[0], bh[1]);
                    mma_bf16(acc[mi][nt * 2 + 1], a_lo[mi], bh[2], bh[3]);
                }
            }
        }
        if (c + 1 < NCHUNK) __syncthreads();
    }

    // ---- epilogue: c0,c1 -> (row g, col..col+1) ; c2,c3 -> row g+8; fp16 out
    const int g = lane >> 2;
    const int q = lane & 3;
#pragma unroll
    for (int mi = 0; mi < 2; mi++) {
        const int rbase = row0 + wm * 32 + mi * 16;
#pragma unroll
        for (int t = 0; t < NT * 2; t++) {
            const int col = wn * WN + t * 8 + q * 2;
            const int r0 = rbase + g;
            const int r1 = rbase + g + 8;
            if (r0 < n)
                *(__half2*)(C16 + (size_t)r0 * FOUT + col) =
                    __floats2half2_rn(acc[mi][t][0], acc[mi][t][1]);
            if (r1 < n)
                *(__half2*)(C16 + (size_t)r1 * FOUT + col) =
                    __floats2half2_rn(acc[mi][t][2], acc[mi][t][3]);
        }
    }
}

// --------------------------- CSR aggregate (fp16 h) -------------------------
// r[v,f] = maybe_relu( in_norm[v] * sum_{e in row v} h16[col_idx[e], f] + b[f] )
// B16OUT: write r*out_norm[v] split into bf16 hi/lo (next layer's A operand).
// else: write fp32 float4 (final output).

template <int F, bool RELU, bool B16OUT>
__global__ void aggregate_kernel(const __half* __restrict__ H,
                                 const float* __restrict__ bias,
                                 float4* __restrict__ out4,
                                 __nv_bfloat16* __restrict__ Ahi,
                                 __nv_bfloat16* __restrict__ Alo,
                                 int n)
{
    constexpr int LPN = F / 4;         // 32 or 16
    constexpr int NPB = 128 / LPN;     // 4 or 8
    const int lane = threadIdx.x % LPN;
    const int slot = threadIdx.x / LPN;
    const int v = blockIdx.x * NPB + slot;
    if (v >= n) return;

    const int beg = g_row_ptr[v];
    const int end = g_row_ptr[v + 1];

    float4 acc0 = make_float4(0.f, 0.f, 0.f, 0.f);
    float4 acc1 = make_float4(0.f, 0.f, 0.f, 0.f);
    int e = beg;
    for (; e + 1 < end; e += 2) {
        const int s0 = g_col_idx[e];
        const int s1 = g_col_idx[e + 1];
        const uint2 u0 = __ldg((const uint2*)(H + (size_t)s0 * F) + lane);
        const uint2 u1 = __ldg((const uint2*)(H + (size_t)s1 * F) + lane);
        const float2 a = __half22float2(*(const __half2*)&u0.x);
        const float2 b = __half22float2(*(const __half2*)&u0.y);
        const float2 c = __half22float2(*(const __half2*)&u1.x);
        const float2 d = __half22float2(*(const __half2*)&u1.y);
        acc0.x += a.x; acc0.y += a.y; acc0.z += b.x; acc0.w += b.y;
        acc1.x += c.x; acc1.y += c.y; acc1.z += d.x; acc1.w += d.y;
    }
    if (e < end) {
        const int s = g_col_idx[e];
        const uint2 u = __ldg((const uint2*)(H + (size_t)s * F) + lane);
        const float2 a = __half22float2(*(const __half2*)&u.x);
        const float2 b = __half22float2(*(const __half2*)&u.y);
        acc0.x += a.x; acc0.y += a.y; acc0.z += b.x; acc0.w += b.y;
    }
    acc0.x += acc1.x; acc0.y += acc1.y; acc0.z += acc1.z; acc0.w += acc1.w;

    const float nm = g_in_norm[v];
    const float4 b4 = __ldg(&((const float4*)bias)[lane]);
    float r[4] = { acc0.x * nm + b4.x, acc0.y * nm + b4.y,
                   acc0.z * nm + b4.z, acc0.w * nm + b4.w };
    if (RELU) {
#pragma unroll
        for (int j = 0; j < 4; j++) r[j] = fmaxf(r[j], 0.f);
    }

    if (B16OUT) {
        const float on = g_out_norm[v];
        BF4 hi, lo;
#pragma unroll
        for (int j = 0; j < 4; j++) {
            const float s = r[j] * on;
            __nv_bfloat16 h = __float2bfloat16_rn(s);
            hi.b[j] = h;
            lo.b[j] = __float2bfloat16_rn(s - __bfloat162float(h));
        }
        *(unsigned long long*)(Ahi + (size_t)v * F + lane * 4) = hi.u64;
        *(unsigned long long*)(Alo + (size_t)v * F + lane * 4) = lo.u64;
    } else {
        out4[(size_t)v * LPN + lane] = make_float4(r[0], r[1], r[2], r[3]);
    }
}

// ------------------------------- launch ------------------------------------

extern "C" void kernel_launch(void* const* d_in, const int* in_sizes, int n_in,
                              void* d_out, int out_size)
{
    const float* x  = (const float*)d_in[0];
    const int*   ei = (const int*)d_in[1];
    const float* W0 = (const float*)d_in[2];
    const float* b0 = (const float*)d_in[3];
    const float* W1 = (const float*)d_in[4];
    const float* b1 = (const float*)d_in[5];
    const float* W2 = (const float*)d_in[6];
    const float* b2 = (const float*)d_in[7];
    const float* W3 = (const float*)d_in[8];
    const float* b3 = (const float*)d_in[9];
    float* out = (float*)d_out;

    const int e = in_sizes[1] / 2;        // 800000 edges
    const int n = in_sizes[0] / 256;      // 50000 nodes

    void* pH = nullptr;
    void* pHi = nullptr;
    void* pLo = nullptr;
    void* pC = nullptr;
    cudaGetSymbolAddress(&pH, g_h16);
    cudaGetSymbolAddress(&pHi, g_ahi);
    cudaGetSymbolAddress(&pLo, g_alo);
    cudaGetSymbolAddress(&pC, g_counts);
    __half* h16 = (__half*)pH;
    __nv_bfloat16* ahi = (__nv_bfloat16*)pHi;
    __nv_bfloat16* alo = (__nv_bfloat16*)pLo;

    const int smem_f128 = 2 * 128 * 144 + 2 * 64 * 272;  // 71680
    const int smem_f64  = 2 * 128 * 144 + 2 * 64 * 144;  // 55296

    static bool inited = false;
    if (!inited) {
        inited = true;
        cudaFuncSetAttribute(gemm_mma_kernel<256, 128, false>,
                             cudaFuncAttributeMaxDynamicSharedMemorySize, smem_f128);
        cudaFuncSetAttribute(gemm_mma_kernel<128, 128, true>,
                             cudaFuncAttributeMaxDynamicSharedMemorySize, smem_f128);
        cudaFuncSetAttribute(gemm_mma_kernel<128, 64, true>,
                             cudaFuncAttributeMaxDynamicSharedMemorySize, smem_f64);
    }

    const int TB = 256;
    const int eg = (e + TB - 1) / TB;

    // ---- setup (4 launches): memset, hist, scan_fill(fused), fill_csr
    cudaMemsetAsync(pC, 0, sizeof(int) * 3 * NN, 0);
    hist_kernel<<<eg, TB>>>(ei, e);
    scan_fill_kernel<<<SCAN_G, SCAN_T>>>(n);
    fill_csr_kernel<<<eg, TB>>>(ei, e);

    const int GB = (n + 127) / 128;   // 391

    // layer 0: 256 -> 128, relu (A from fp32 X)
    gemm_mma_kernel<256, 128, false><<<GB, 256, smem_f128>>>(x, nullptr, nullptr, W0, h16, n);
    aggregate_kernel<128, true, true><<<(n + 3) / 4, 128>>>(h16, b0, nullptr, ahi, alo, n);

    // layer 1: 128 -> 128, relu (A from bf16 hi/lo)
    gemm_mma_kernel<128, 128, true><<<GB, 256, smem_f128>>>(nullptr, ahi, alo, W1, h16, n);
    aggregate_kernel<128, true, true><<<(n + 3) / 4, 128>>>(h16, b1, nullptr, ahi, alo, n);

    // layer 2: 128 -> 128, relu
    gemm_mma_kernel<128, 128, true><<<GB, 256, smem_f128>>>(nullptr, ahi, alo, W2, h16, n);
    aggregate_kernel<128, true, true><<<(n + 3) / 4, 128>>>(h16, b2, nullptr, ahi, alo, n);

    // layer 3: 128 -> 64, no relu, fp32 out
    gemm_mma_kernel<128, 64, true><<<GB, 256, smem_f64>>>(nullptr, ahi, alo, W3, h16, n);
    aggregate_kernel<64, false, false><<<(n + 7) / 8, 128>>>(h16, b3, (float4*)out, nullptr, nullptr, n);
}

// round 14
// speedup vs baseline: 1.0936x; 1.0559x over previous
#include <cuda_runtime.h>
#include <cuda_bf16.h>
#include <cuda_fp16.h>
#include <cstdint>

// ---------------------------------------------------------------------------
// 4-layer GCN. GEMM: mma.sync.m16n8k16 bf16 split-precision (hi*hi + hi*lo +
// lo*hi, fp32 accum), 2 CTAs/SM via __launch_bounds__(256,2), weights
// pre-split to bf16 hi/lo once per launch. h stored fp16; aggregates emit
// next layer's A operand pre-scaled as bf16 hi/lo. Setup: memset, hist
// (inline dtype probe), scan_fill (norms+base+scan fused), fill_csr, split_w.
// ---------------------------------------------------------------------------

#define NN 50000
#define NE 800000
#define SCAN_T 256
#define SCAN_G ((NN + SCAN_T - 1) / SCAN_T)   // 196

// weight layout offsets inside the packed hi/lo buffers
#define W0_OFF 0
#define W1_OFF (256 * 128)
#define W2_OFF (W1_OFF + 128 * 128)
#define W3_OFF (W2_OFF + 128 * 128)
#define W_TOT  (W3_OFF + 128 * 64)            // 73728

// scratch (device globals: no allocation allowed)
__device__ __half         g_h16[NN * 128];    // GEMM output, pre-aggregation
__device__ __nv_bfloat16  g_ahi[NN * 128];    // aggregate out: bf16 hi
__device__ __nv_bfloat16  g_alo[NN * 128];    // aggregate out: bf16 lo
__device__ __nv_bfloat16  g_whi[W_TOT];       // weights: bf16 hi
__device__ __nv_bfloat16  g_wlo[W_TOT];       // weights: bf16 lo
__device__ float  g_out_norm[NN];
__device__ float  g_in_norm[NN];
__device__ int    g_counts[3 * NN];           // [out_deg | in_deg | cursor]
__device__ int    g_row_ptr[NN + 1];
__device__ int    g_col_idx[NE];

#define OUT_DEG(i) g_counts[(i)]
#define IN_DEG(i)  g_counts[NN + (i)]
#define CURSOR(i)  g_counts[2 * NN + (i)]

// ============================ PTX helpers ===================================

__device__ __forceinline__ uint32_t smem_u32(const void* p) {
    uint32_t a;
    asm("{ .reg .u64 t; cvta.to.shared.u64 t, %1; cvt.u32.u64 %0, t; }"
        : "=r"(a) : "l"(p));
    return a;
}

__device__ __forceinline__ void ldsm_x4(uint32_t* r, uint32_t addr) {
    asm volatile("ldmatrix.sync.aligned.m8n8.x4.shared.b16 {%0,%1,%2,%3}, [%4];"
                 : "=r"(r[0]), "=r"(r[1]), "=r"(r[2]), "=r"(r[3]) : "r"(addr));
}

__device__ __forceinline__ void ldsm_x4_t(uint32_t* r, uint32_t addr) {
    asm volatile("ldmatrix.sync.aligned.m8n8.x4.trans.shared.b16 {%0,%1,%2,%3}, [%4];"
                 : "=r"(r[0]), "=r"(r[1]), "=r"(r[2]), "=r"(r[3]) : "r"(addr));
}

__device__ __forceinline__ void mma_bf16(float* c, const uint32_t* a,
                                         uint32_t b0, uint32_t b1) {
    asm volatile(
        "mma.sync.aligned.m16n8k16.row.col.f32.bf16.bf16.f32 "
        "{%0,%1,%2,%3}, {%4,%5,%6,%7}, {%8,%9}, {%0,%1,%2,%3};"
        : "+f"(c[0]), "+f"(c[1]), "+f"(c[2]), "+f"(c[3])
        : "r"(a[0]), "r"(a[1]), "r"(a[2]), "r"(a[3]), "r"(b0), "r"(b1));
}

union BF4 {
    unsigned long long u64;
    __nv_bfloat16 b[4];
};

// =================== histogram with inline dtype probe ======================
// JAX with x64 disabled silently emits int32 for edge_index despite jnp.int64.

__device__ __forceinline__ int probe_is64(const int* __restrict__ w) {
    int flag = 0;
    if (threadIdx.x < 64) flag = (w[2 * threadIdx.x + 1] != 0);
    return !__syncthreads_or(flag);
}

__device__ __forceinline__ void load_edge(const int* __restrict__ w, int e,
                                          int is64, int i, int& s, int& d) {
    if (is64) {
        const long long* p = (const long long*)w;
        s = (int)p[i];
        d = (int)p[e + i];
    } else {
        s = w[i];
        d = w[e + i];
    }
}

__global__ void hist_kernel(const int* __restrict__ w, int e) {
    const int is64 = probe_is64(w);
    const int i = blockIdx.x * blockDim.x + threadIdx.x;
    if (i >= e) return;
    int s, d;
    load_edge(w, e, is64, i, s, d);
    atomicAdd(&OUT_DEG(s), 1);
    atomicAdd(&IN_DEG(d), 1);
}

// ---- fused: norms + per-block exclusive base (direct IN_DEG sum) + scan ----

__global__ void scan_fill_kernel(int n) {
    __shared__ int sh[SCAN_T];
    __shared__ int base_sh;
    const int tid = threadIdx.x;

    const int blk_start = blockIdx.x * SCAN_T;
    int partial = 0;
    for (int i = tid; i < blk_start; i += SCAN_T) partial += IN_DEG(i);
    sh[tid] = partial;
    __syncthreads();
    for (int off = 128; off > 0; off >>= 1) {
        if (tid < off) sh[tid] += sh[tid + off];
        __syncthreads();
    }
    if (tid == 0) base_sh = sh[0];
    __syncthreads();
    const int base = base_sh;
    __syncthreads();

    const int i = blk_start + tid;
    int d = 0;
    if (i < n) {
        d = IN_DEG(i);
        g_in_norm[i]  = rsqrtf((float)max(d, 1));
        g_out_norm[i] = rsqrtf((float)max(OUT_DEG(i), 1));
    }
    sh[tid] = d;
    __syncthreads();
    for (int off = 1; off < SCAN_T; off <<= 1) {
        int v = (tid >= off) ? sh[tid - off] : 0;
        __syncthreads();
        sh[tid] += v;
        __syncthreads();
    }
    if (i < n) {
        const int incl = sh[tid];
        g_row_ptr[i] = base + incl - d;
        if (i == n - 1) g_row_ptr[n] = base + incl;
    }
}

__global__ void fill_csr_kernel(const int* __restrict__ w, int e) {
    const int is64 = probe_is64(w);
    const int i = blockIdx.x * blockDim.x + threadIdx.x;
    if (i >= e) return;
    int s, d;
    load_edge(w, e, is64, i, s, d);
    const int pos = g_row_ptr[d] + atomicAdd(&CURSOR(d), 1);
    g_col_idx[pos] = s;
}

// ------------------- weight split: fp32 -> bf16 hi/lo -----------------------

__global__ void split_w_kernel(const float* __restrict__ W0,
                               const float* __restrict__ W1,
                               const float* __restrict__ W2,
                               const float* __restrict__ W3)
{
    const int i = blockIdx.x * blockDim.x + threadIdx.x;
    if (i >= W_TOT) return;
    float v;
    if      (i < W1_OFF) v = W0[i];
    else if (i < W2_OFF) v = W1[i - W1_OFF];
    else if (i < W3_OFF) v = W2[i - W2_OFF];
    else                 v = W3[i - W3_OFF];
    const __nv_bfloat16 h = __float2bfloat16_rn(v);
    g_whi[i] = h;
    g_wlo[i] = __float2bfloat16_rn(v - __bfloat162float(h));
}

// ================== bf16 split-precision mma.sync GEMM ======================
// C16[n,FOUT] = fp16( A @ W[FIN,FOUT] ); A = X*out_norm (fp32 path, A16=false)
// or pre-split bf16 hi/lo (A16=true). W pre-split bf16 hi/lo in gmem.
// BM=128 rows/CTA, BK=64. 8 warps: 4(m) x 2(n); 2 CTAs/SM via launch_bounds.

template <int FIN, int FOUT, bool A16>
__global__ __launch_bounds__(256, 2) void gemm_mma_kernel(
    const float* __restrict__ X,
    const __nv_bfloat16* __restrict__ Ahi,
    const __nv_bfloat16* __restrict__ Alo,
    const __nv_bfloat16* __restrict__ Whi,
    const __nv_bfloat16* __restrict__ Wlo,
    __half* __restrict__ C16, int n)
{
    constexpr int BK = 64;
    constexpr int NCHUNK = FIN / BK;
    constexpr int RS_A = BK * 2 + 16;          // 144 B
    constexpr int RS_B = FOUT * 2 + 16;        // 272 or 144 B
    constexpr int A_SZ = 128 * RS_A;
    constexpr int B_SZ = BK * RS_B;
    constexpr int SM_A_HI = 0;
    constexpr int SM_A_LO = A_SZ;
    constexpr int SM_B_HI = 2 * A_SZ;
    constexpr int SM_B_LO = 2 * A_SZ + B_SZ;
    constexpr int WN = FOUT / 2;               // warp n-extent: 64 or 32
    constexpr int NT = WN / 16;                // x4.trans units: 4 or 2

    extern __shared__ char smem[];
    const uint32_t sb = smem_u32(smem);
    const int tid  = threadIdx.x;
    const int wid  = tid >> 5;
    const int lane = tid & 31;
    const int wm   = wid & 3;
    const int wn   = wid >> 2;
    const int row0 = blockIdx.x * 128;

    float acc[2][NT * 2][4];
#pragma unroll
    for (int mi = 0; mi < 2; mi++)
#pragma unroll
        for (int t = 0; t < NT * 2; t++)
#pragma unroll
            for (int j = 0; j < 4; j++) acc[mi][t][j] = 0.0f;

    for (int c = 0; c < NCHUNK; ++c) {
        const int k0 = c * BK;

        // ---- A chunk: 128 rows x 64 k -> smem hi/lo
        if (A16) {
            // 16B vector copies: 128 rows x 8 uint4 (hi) + same (lo)
            for (int idx = tid; idx < 128 * (BK / 8); idx += 256) {
                const int r  = idx >> 3;
                const int k  = (idx & 7) * 8;
                const int gr = row0 + r;
                uint4 hi = make_uint4(0, 0, 0, 0), lo = make_uint4(0, 0, 0, 0);
                if (gr < n) {
                    hi = *(const uint4*)(Ahi + (size_t)gr * FIN + k0 + k);
                    lo = *(const uint4*)(Alo + (size_t)gr * FIN + k0 + k);
                }
                const uint32_t off = (uint32_t)(r * RS_A + k * 2);
                *(uint4*)(smem + SM_A_HI + off) = hi;
                *(uint4*)(smem + SM_A_LO + off) = lo;
            }
        } else {
            for (int idx = tid; idx < 128 * (BK / 4); idx += 256) {
                const int r  = idx >> 4;
                const int k  = (idx & 15) * 4;
                const int gr = row0 + r;
                float4 xv = make_float4(0.f, 0.f, 0.f, 0.f);
                float s = 0.f;
                if (gr < n) {
                    xv = __ldg((const float4*)(X + (size_t)gr * FIN + k0 + k));
                    s = g_out_norm[gr];
                }
                float v[4] = { xv.x * s, xv.y * s, xv.z * s, xv.w * s };
                BF4 hi, lo;
#pragma unroll
                for (int j = 0; j < 4; j++) {
                    __nv_bfloat16 h = __float2bfloat16_rn(v[j]);
                    hi.b[j] = h;
                    lo.b[j] = __float2bfloat16_rn(v[j] - __bfloat162float(h));
                }
                const uint32_t off = (uint32_t)(r * RS_A + k * 2);
                *(unsigned long long*)(smem + SM_A_HI + off) = hi.u64;
                *(unsigned long long*)(smem + SM_A_LO + off) = lo.u64;
            }
        }

        // ---- B chunk: 64 k-rows x FOUT from pre-split gmem, 16B copies
        for (int idx = tid; idx < BK * (FOUT / 8); idx += 256) {
            const int k  = idx / (FOUT / 8);
            const int nn = (idx % (FOUT / 8)) * 8;
            const size_t g = (size_t)(k0 + k) * FOUT + nn;
            const uint4 hi = *(const uint4*)(Whi + g);
            const uint4 lo = *(const uint4*)(Wlo + g);
            const uint32_t off = (uint32_t)(k * RS_B + nn * 2);
            *(uint4*)(smem + SM_B_HI + off) = hi;
            *(uint4*)(smem + SM_B_LO + off) = lo;
        }

        __syncthreads();

        // ---- MMA over 4 k-steps of 16
#pragma unroll
        for (int ks = 0; ks < 4; ks++) {
            const int kk = ks * 16;
            uint32_t a_hi[2][4], a_lo[2][4];
#pragma unroll
            for (int mi = 0; mi < 2; mi++) {
                const int r = wm * 32 + mi * 16 + (lane & 15);
                const int col = kk + ((lane >> 4) << 3);
                const uint32_t off = (uint32_t)(r * RS_A + col * 2);
                ldsm_x4(a_hi[mi], sb + SM_A_HI + off);
                ldsm_x4(a_lo[mi], sb + SM_A_LO + off);
            }
#pragma unroll
            for (int nt = 0; nt < NT; nt++) {
                const int k = kk + (lane & 15);
                const int nn = wn * WN + nt * 16 + ((lane >> 4) << 3);
                const uint32_t off = (uint32_t)(k * RS_B + nn * 2);
                uint32_t bh[4], bl[4];
                ldsm_x4_t(bh, sb + SM_B_HI + off);
                ldsm_x4_t(bl, sb + SM_B_LO + off);
#pragma unroll
                for (int mi = 0; mi < 2; mi++) {
                    mma_bf16(acc[mi][nt * 2 + 0], a_hi[mi], bh[0], bh[1]);
                    mma_bf16(acc[mi][nt * 2 + 1], a_hi[mi], bh[2], bh[3]);
                    mma_bf16(acc[mi][nt * 2 + 0], a_hi[mi], bl[0], bl[1]);
                    mma_bf16(acc[mi][nt * 2 + 1], a_hi[mi], bl[2], bl[3]);
                    mma_bf16(acc[mi][nt * 2 + 0], a_lo[mi], bh[0], bh[1]);
                    mma_bf16(acc[mi][nt * 2 + 1], a_lo[mi], bh[2], bh[3]);
                }
            }
        }
        if (c + 1 < NCHUNK) __syncthreads();
    }

    // ---- epilogue: c0,c1 -> (row g, col..col+1) ; c2,c3 -> row g+8; fp16 out
    const int g = lane >> 2;
    const int q = lane & 3;
#pragma unroll
    for (int mi = 0; mi < 2; mi++) {
        const int rbase = row0 + wm * 32 + mi * 16;
#pragma unroll
        for (int t = 0; t < NT * 2; t++) {
            const int col = wn * WN + t * 8 + q * 2;
            const int r0 = rbase + g;
            const int r1 = rbase + g + 8;
            if (r0 < n)
                *(__half2*)(C16 + (size_t)r0 * FOUT + col) =
                    __floats2half2_rn(acc[mi][t][0], acc[mi][t][1]);
            if (r1 < n)
                *(__half2*)(C16 + (size_t)r1 * FOUT + col) =
                    __floats2half2_rn(acc[mi][t][2], acc[mi][t][3]);
        }
    }
}

// --------------------------- CSR aggregate (fp16 h) -------------------------
// r[v,f] = maybe_relu( in_norm[v] * sum_{e in row v} h16[col_idx[e], f] + b[f] )
// B16OUT: write r*out_norm[v] split into bf16 hi/lo (next layer's A operand).

template <int F, bool RELU, bool B16OUT>
__global__ void aggregate_kernel(const __half* __restrict__ H,
                                 const float* __restrict__ bias,
                                 float4* __restrict__ out4,
                                 __nv_bfloat16* __restrict__ Ahi,
                                 __nv_bfloat16* __restrict__ Alo,
                                 int n)
{
    constexpr int LPN = F / 4;         // 32 or 16
    constexpr int NPB = 128 / LPN;     // 4 or 8
    const int lane = threadIdx.x % LPN;
    const int slot = threadIdx.x / LPN;
    const int v = blockIdx.x * NPB + slot;
    if (v >= n) return;

    const int beg = g_row_ptr[v];
    const int end = g_row_ptr[v + 1];

    float4 acc0 = make_float4(0.f, 0.f, 0.f, 0.f);
    float4 acc1 = make_float4(0.f, 0.f, 0.f, 0.f);
    int e = beg;
    for (; e + 1 < end; e += 2) {
        const int s0 = g_col_idx[e];
        const int s1 = g_col_idx[e + 1];
        const uint2 u0 = __ldg((const uint2*)(H + (size_t)s0 * F) + lane);
        const uint2 u1 = __ldg((const uint2*)(H + (size_t)s1 * F) + lane);
        const float2 a = __half22float2(*(const __half2*)&u0.x);
        const float2 b = __half22float2(*(const __half2*)&u0.y);
        const float2 c = __half22float2(*(const __half2*)&u1.x);
        const float2 d = __half22float2(*(const __half2*)&u1.y);
        acc0.x += a.x; acc0.y += a.y; acc0.z += b.x; acc0.w += b.y;
        acc1.x += c.x; acc1.y += c.y; acc1.z += d.x; acc1.w += d.y;
    }
    if (e < end) {
        const int s = g_col_idx[e];
        const uint2 u = __ldg((const uint2*)(H + (size_t)s * F) + lane);
        const float2 a = __half22float2(*(const __half2*)&u.x);
        const float2 b = __half22float2(*(const __half2*)&u.y);
        acc0.x += a.x; acc0.y += a.y; acc0.z += b.x; acc0.w += b.y;
    }
    acc0.x += acc1.x; acc0.y += acc1.y; acc0.z += acc1.z; acc0.w += acc1.w;

    const float nm = g_in_norm[v];
    const float4 b4 = __ldg(&((const float4*)bias)[lane]);
    float r[4] = { acc0.x * nm + b4.x, acc0.y * nm + b4.y,
                   acc0.z * nm + b4.z, acc0.w * nm + b4.w };
    if (RELU) {
#pragma unroll
        for (int j = 0; j < 4; j++) r[j] = fmaxf(r[j], 0.f);
    }

    if (B16OUT) {
        const float on = g_out_norm[v];
        BF4 hi, lo;
#pragma unroll
        for (int j = 0; j < 4; j++) {
            const float s = r[j] * on;
            __nv_bfloat16 h = __float2bfloat16_rn(s);
            hi.b[j] = h;
            lo.b[j] = __float2bfloat16_rn(s - __bfloat162float(h));
        }
        *(unsigned long long*)(Ahi + (size_t)v * F + lane * 4) = hi.u64;
        *(unsigned long long*)(Alo + (size_t)v * F + lane * 4) = lo.u64;
    } else {
        out4[(size_t)v * LPN + lane] = make_float4(r[0], r[1], r[2], r[3]);
    }
}

// ------------------------------- launch ------------------------------------

extern "C" void kernel_launch(void* const* d_in, const int* in_sizes, int n_in,
                              void* d_out, int out_size)
{
    const float* x  = (const float*)d_in[0];
    const int*   ei = (const int*)d_in[1];
    const float* W0 = (const float*)d_in[2];
    const float* b0 = (const float*)d_in[3];
    const float* W1 = (const float*)d_in[4];
    const float* b1 = (const float*)d_in[5];
    const float* W2 = (const float*)d_in[6];
    const float* b2 = (const float*)d_in[7];
    const float* W3 = (const float*)d_in[8];
    const float* b3 = (const float*)d_in[9];
    float* out = (float*)d_out;

    const int e = in_sizes[1] / 2;        // 800000 edges
    const int n = in_sizes[0] / 256;      // 50000 nodes

    void* pH = nullptr;
    void* pHi = nullptr;
    void* pLo = nullptr;
    void* pC = nullptr;
    void* pWh = nullptr;
    void* pWl = nullptr;
    cudaGetSymbolAddress(&pH, g_h16);
    cudaGetSymbolAddress(&pHi, g_ahi);
    cudaGetSymbolAddress(&pLo, g_alo);
    cudaGetSymbolAddress(&pC, g_counts);
    cudaGetSymbolAddress(&pWh, g_whi);
    cudaGetSymbolAddress(&pWl, g_wlo);
    __half* h16 = (__half*)pH;
    __nv_bfloat16* ahi = (__nv_bfloat16*)pHi;
    __nv_bfloat16* alo = (__nv_bfloat16*)pLo;
    const __nv_bfloat16* wh = (const __nv_bfloat16*)pWh;
    const __nv_bfloat16* wl = (const __nv_bfloat16*)pWl;

    const int smem_f128 = 2 * 128 * 144 + 2 * 64 * 272;  // 71680
    const int smem_f64  = 2 * 128 * 144 + 2 * 64 * 144;  // 55296

    static bool inited = false;
    if (!inited) {
        inited = true;
        cudaFuncSetAttribute(gemm_mma_kernel<256, 128, false>,
                             cudaFuncAttributeMaxDynamicSharedMemorySize, smem_f128);
        cudaFuncSetAttribute(gemm_mma_kernel<128, 128, true>,
                             cudaFuncAttributeMaxDynamicSharedMemorySize, smem_f128);
        cudaFuncSetAttribute(gemm_mma_kernel<128, 64, true>,
                             cudaFuncAttributeMaxDynamicSharedMemorySize, smem_f64);
    }

    const int TB = 256;
    const int eg = (e + TB - 1) / TB;

    // ---- setup: memset, weight split, hist, scan_fill(fused), fill_csr
    cudaMemsetAsync(pC, 0, sizeof(int) * 3 * NN, 0);
    split_w_kernel<<<(W_TOT + TB - 1) / TB, TB>>>(W0, W1, W2, W3);
    hist_kernel<<<eg, TB>>>(ei, e);
    scan_fill_kernel<<<SCAN_G, SCAN_T>>>(n);
    fill_csr_kernel<<<eg, TB>>>(ei, e);

    const int GB = (n + 127) / 128;   // 391

    // layer 0: 256 -> 128, relu (A from fp32 X)
    gemm_mma_kernel<256, 128, false><<<GB, 256, smem_f128>>>(
        x, nullptr, nullptr, wh + W0_OFF, wl + W0_OFF, h16, n);
    aggregate_kernel<128, true, true><<<(n + 3) / 4, 128>>>(h16, b0, nullptr, ahi, alo, n);

    // layer 1: 128 -> 128, relu (A from bf16 hi/lo)
    gemm_mma_kernel<128, 128, true><<<GB, 256, smem_f128>>>(
        nullptr, ahi, alo, wh + W1_OFF, wl + W1_OFF, h16, n);
    aggregate_kernel<128, true, true><<<(n + 3) / 4, 128>>>(h16, b1, nullptr, ahi, alo, n);

    // layer 2: 128 -> 128, relu
    gemm_mma_kernel<128, 128, true><<<GB, 256, smem_f128>>>(
        nullptr, ahi, alo, wh + W2_OFF, wl + W2_OFF, h16, n);
    aggregate_kernel<128, true, true><<<(n + 3) / 4, 128>>>(h16, b2, nullptr, ahi, alo, n);

    // layer 3: 128 -> 64, no relu, fp32 out
    gemm_mma_kernel<128, 64, true><<<GB, 256, smem_f64>>>(
        nullptr, ahi, alo, wh + W3_OFF, wl + W3_OFF, h16, n);
    aggregate_kernel<64, false, false><<<(n + 7) / 8, 128>>>(h16, b3, (float4*)out, nullptr, nullptr, n);
}